// round 16
// baseline (speedup 1.0000x reference)
#include <cuda_runtime.h>
#include <cuda_bf16.h>
#include <cfloat>
#include <climits>
#include <cstdint>

#define D        512
#define KCB      1024
#define NROWS    65536
#define MARGIN   1.5f
#define CAP      65536

#define BM       128            // rows per CTA
#define BN       128            // codewords per phase
#define NPH      8              // 1024 / 128
#define KC       64             // K elems per stage
#define NSTG     (NPH * (D / KC))   // 64
#define NTH      256

// smem layout (bytes) — 76 KB/CTA -> 2 CTAs per SM
#define SM_C2    0               // float[1024]
#define SM_BUF   4096
#define STRIDE_B 144             // 128B data + 16B pad -> conflict-free ldmatrix
#define A_BYTES  (BM * STRIDE_B)          // 18432
#define B_BYTES  (BN * STRIDE_B)          // 18432
#define BUF_BYTES (A_BYTES + B_BYTES)     // 36864
#define SM_TOTAL (SM_BUF + 2 * BUF_BYTES) // 77824
// reduction scratch aliases the (finished) stage buffers at SM_BUF

// ---- device scratch (no cudaMalloc allowed) ----
__device__ __nv_bfloat16 g_xhi[(size_t)NROWS * D];   // 64 MB
__device__ __nv_bfloat16 g_cbhi[KCB * D];            // 1 MB
__device__ float g_c2[KCB];
__device__ int   g_flag_rows[CAP];                   // full-rescue rows
__device__ int   g_flag_count;
__device__ int4  g_cand[CAP];                        // {row, c0, c1, -}
__device__ int   g_cand_count;

// ================= PTX helpers (baseline sm_80 features only) =================
__device__ __forceinline__ uint32_t smem_u32(const void* p) {
    uint32_t a;
    asm("{ .reg .u64 t; cvta.to.shared.u64 t, %1; cvt.u32.u64 %0, t; }" : "=r"(a) : "l"(p));
    return a;
}
#define CP16(s, g)   asm volatile("cp.async.ca.shared.global [%0], [%1], 16;" :: "r"(s), "l"(g))
#define CPCOMMIT()   asm volatile("cp.async.commit_group;")
#define CPWAIT0()    asm volatile("cp.async.wait_group 0;")
#define LDSM4(r0, r1, r2, r3, a) \
    asm volatile("ldmatrix.sync.aligned.m8n8.x4.shared.b16 {%0,%1,%2,%3}, [%4];" \
                 : "=r"(r0), "=r"(r1), "=r"(r2), "=r"(r3) : "r"(a))

__device__ __forceinline__ void mma_bf16(float* c, const uint32_t* a, uint32_t b0, uint32_t b1) {
    asm volatile(
        "mma.sync.aligned.m16n8k16.row.col.f32.bf16.bf16.f32 "
        "{%0,%1,%2,%3}, {%4,%5,%6,%7}, {%8,%9}, {%0,%1,%2,%3};"
        : "+f"(c[0]), "+f"(c[1]), "+f"(c[2]), "+f"(c[3])
        : "r"(a[0]), "r"(a[1]), "r"(a[2]), "r"(a[3]), "r"(b0), "r"(b1));
}

// sorted top-3 insert by (value, index); first-occurrence tie semantics
__device__ __forceinline__ void ins3(float* v, int* i, float nv, int ni) {
    if (nv < v[2] || (nv == v[2] && ni < i[2])) {
        if (nv < v[1] || (nv == v[1] && ni < i[1])) {
            v[2] = v[1]; i[2] = i[1];
            if (nv < v[0] || (nv == v[0] && ni < i[0])) {
                v[1] = v[0]; i[1] = i[0]; v[0] = nv; i[0] = ni;
            } else { v[1] = nv; i[1] = ni; }
        } else { v[2] = nv; i[2] = ni; }
    }
}

// ================= prep: f32 -> bf16 hi =================
__global__ __launch_bounds__(512) void prep_x(const float* __restrict__ x) {
    size_t i = (size_t)blockIdx.x * 512 + threadIdx.x;     // over float4s
    float4 v = reinterpret_cast<const float4*>(x)[i];
    __nv_bfloat162 h01 = __floats2bfloat162_rn(v.x, v.y);
    __nv_bfloat162 h23 = __floats2bfloat162_rn(v.z, v.w);
    uint2 hw;
    hw.x = *reinterpret_cast<uint32_t*>(&h01); hw.y = *reinterpret_cast<uint32_t*>(&h23);
    reinterpret_cast<uint2*>(g_xhi)[i] = hw;
}
__global__ __launch_bounds__(512) void prep_cb(const float* __restrict__ cb) {
    size_t i = (size_t)blockIdx.x * 512 + threadIdx.x;
    float4 v = reinterpret_cast<const float4*>(cb)[i];
    __nv_bfloat162 h01 = __floats2bfloat162_rn(v.x, v.y);
    __nv_bfloat162 h23 = __floats2bfloat162_rn(v.z, v.w);
    uint2 hw;
    hw.x = *reinterpret_cast<uint32_t*>(&h01); hw.y = *reinterpret_cast<uint32_t*>(&h23);
    reinterpret_cast<uint2*>(g_cbhi)[i] = hw;
}

// ================= pass 0: ||c||^2 (fp64 accum) + reset counters =================
__global__ void c2_kernel(const float* __restrict__ cb) {
    if (blockIdx.x == 0 && threadIdx.x == 0) { g_flag_count = 0; g_cand_count = 0; }
    int cw   = blockIdx.x * (blockDim.x >> 5) + (threadIdx.x >> 5);
    int lane = threadIdx.x & 31;
    const float4* p = reinterpret_cast<const float4*>(cb + (size_t)cw * D);
    double s = 0.0;
    for (int t = lane; t < D / 4; t += 32) {
        float4 v = p[t];
        s += (double)v.x * v.x + (double)v.y * v.y + (double)v.z * v.z + (double)v.w * v.w;
    }
    #pragma unroll
    for (int o = 16; o; o >>= 1) s += __shfl_xor_sync(0xffffffffu, s, o);
    if (lane == 0) g_c2[cw] = (float)s;
}

// ================= pass A: GEMM screen + fused top-3 + output =================
__device__ __forceinline__ void stage_load(int s, int rowbase, uint32_t sbase, int tid) {
    const int ph = s >> 3;
    const int k0 = (s & 7) * KC;
    const uint32_t bufo = sbase + SM_BUF + (uint32_t)(s & 1) * BUF_BYTES;
    #pragma unroll
    for (int i = 0; i < 4; ++i) {                 // A: 128 rows x 8 chunks of 16B
        int id = tid + i * NTH;
        int row = id >> 3, kc = id & 7;
        CP16(bufo + row * STRIDE_B + kc * 16,
             g_xhi + (size_t)(rowbase + row) * D + k0 + kc * 8);
    }
    #pragma unroll
    for (int i = 0; i < 4; ++i) {                 // B: 128 rows x 8 chunks of 16B
        int id = tid + i * NTH;
        int n = id >> 3, kc = id & 7;
        CP16(bufo + A_BYTES + n * STRIDE_B + kc * 16,
             g_cbhi + (size_t)(ph * BN + n) * D + k0 + kc * 8);
    }
    CPCOMMIT();
}

__global__ __launch_bounds__(NTH, 2) void vq_gemm_kernel(
    const float* __restrict__ cb,
    float* __restrict__ out)
{
    extern __shared__ char smem[];
    const uint32_t sbase = smem_u32(smem);
    const int tid   = threadIdx.x;
    const int lane  = tid & 31;
    const int wid   = tid >> 5;
    const int mwarp = wid >> 1;       // 0..3 -> 32 rows each
    const int nwarp = wid & 1;        // 0..1 -> 64 cols each
    const int rowbase = blockIdx.x * BM;

    float* s_c2 = reinterpret_cast<float*>(smem + SM_C2);
    for (int i = tid; i < KCB; i += NTH) s_c2[i] = g_c2[i];

    // reduction scratch aliases stage buffers (used only after main loop)
    float* s_t3v = reinterpret_cast<float*>(smem + SM_BUF);             // [2][128][3]
    int*   s_t3i = reinterpret_cast<int*>(smem + SM_BUF + 3072);        // [2][128][3]
    int*   s_win = reinterpret_cast<int*>(smem + SM_BUF + 6144);        // [128]

    // per-thread ldmatrix offsets
    uint32_t aoff[2], boff[4];
    #pragma unroll
    for (int mt = 0; mt < 2; ++mt) {
        int row = mwarp * 32 + mt * 16 + (lane & 7) + ((lane >> 3) & 1) * 8;
        aoff[mt] = row * STRIDE_B + (lane >> 4) * 16;
    }
    #pragma unroll
    for (int p = 0; p < 4; ++p) {
        int n = nwarp * 64 + p * 16 + (lane & 7) + (lane >> 4) * 8;
        boff[p] = A_BYTES + n * STRIDE_B + ((lane >> 3) & 1) * 16;
    }

    float acc[2][8][4];
    float t3v[4][3];     // per row-slot top-3 values
    int   t3i[4][3];     // per row-slot top-3 indices
    #pragma unroll
    for (int r = 0; r < 4; ++r)
        #pragma unroll
        for (int k = 0; k < 3; ++k) { t3v[r][k] = FLT_MAX; t3i[r][k] = INT_MAX; }

    stage_load(0, rowbase, sbase, tid);

    for (int s = 0; s < NSTG; ++s) {
        CPWAIT0();
        __syncthreads();
        if (s + 1 < NSTG) stage_load(s + 1, rowbase, sbase, tid);

        if ((s & 7) == 0) {
            #pragma unroll
            for (int mt = 0; mt < 2; ++mt)
                #pragma unroll
                for (int nt = 0; nt < 8; ++nt)
                    #pragma unroll
                    for (int r = 0; r < 4; ++r) acc[mt][nt][r] = 0.f;
        }

        const uint32_t bufo = sbase + SM_BUF + (uint32_t)(s & 1) * BUF_BYTES;
        #pragma unroll
        for (int ks = 0; ks < 4; ++ks) {
            uint32_t a0[4], a1[4];
            LDSM4(a0[0], a0[1], a0[2], a0[3], bufo + aoff[0] + ks * 32);
            LDSM4(a1[0], a1[1], a1[2], a1[3], bufo + aoff[1] + ks * 32);
            #pragma unroll
            for (int p = 0; p < 4; ++p) {
                uint32_t b0, b1, b2, b3;
                LDSM4(b0, b1, b2, b3, bufo + boff[p] + ks * 32);
                mma_bf16(acc[0][2 * p],     a0, b0, b1);
                mma_bf16(acc[0][2 * p + 1], a0, b2, b3);
                mma_bf16(acc[1][2 * p],     a1, b0, b1);
                mma_bf16(acc[1][2 * p + 1], a1, b2, b3);
            }
        }

        if ((s & 7) == 7) {   // phase epilogue: scores -> top-3 (cols ascending)
            const int ph = s >> 3;
            const int cbase = ph * BN + nwarp * 64 + (lane & 3) * 2;
            #pragma unroll
            for (int mt = 0; mt < 2; ++mt) {
                #pragma unroll
                for (int nt = 0; nt < 8; ++nt) {
                    const int col0 = cbase + nt * 8;
                    const float c2a = s_c2[col0], c2b = s_c2[col0 + 1];
                    const float* a = acc[mt][nt];
                    ins3(t3v[mt * 2],     t3i[mt * 2],     fmaf(-2.f, a[0], c2a), col0);
                    ins3(t3v[mt * 2],     t3i[mt * 2],     fmaf(-2.f, a[1], c2b), col0 + 1);
                    ins3(t3v[mt * 2 + 1], t3i[mt * 2 + 1], fmaf(-2.f, a[2], c2a), col0);
                    ins3(t3v[mt * 2 + 1], t3i[mt * 2 + 1], fmaf(-2.f, a[3], c2b), col0 + 1);
                }
            }
        }
    }

    // quad merge (4 lanes per row share cols)
    #pragma unroll
    for (int off = 1; off <= 2; off <<= 1) {
        #pragma unroll
        for (int r = 0; r < 4; ++r) {
            float ov[3]; int oi[3];
            #pragma unroll
            for (int k = 0; k < 3; ++k) {
                ov[k] = __shfl_xor_sync(0xffffffffu, t3v[r][k], off);
                oi[k] = __shfl_xor_sync(0xffffffffu, t3i[r][k], off);
            }
            #pragma unroll
            for (int k = 0; k < 3; ++k) ins3(t3v[r], t3i[r], ov[k], oi[k]);
        }
    }
    __syncthreads();   // main-loop buffer reads done; safe to alias as scratch
    if ((lane & 3) == 0) {
        #pragma unroll
        for (int r = 0; r < 4; ++r) {
            int rowloc = mwarp * 32 + (lane >> 2) + ((r & 1) ? 8 : 0) + ((r >> 1) ? 16 : 0);
            #pragma unroll
            for (int k = 0; k < 3; ++k) {
                s_t3v[(nwarp * 128 + rowloc) * 3 + k] = t3v[r][k];
                s_t3i[(nwarp * 128 + rowloc) * 3 + k] = t3i[r][k];
            }
        }
    }
    __syncthreads();

    if (tid < BM) {
        float mv[3]; int mi[3];
        #pragma unroll
        for (int k = 0; k < 3; ++k) { mv[k] = s_t3v[tid * 3 + k]; mi[k] = s_t3i[tid * 3 + k]; }
        #pragma unroll
        for (int k = 0; k < 3; ++k)
            ins3(mv, mi, s_t3v[(128 + tid) * 3 + k], s_t3i[(128 + tid) * 3 + k]);

        const int row = rowbase + tid;
        int win = mi[0];
        if (mv[2] < mv[0] + MARGIN) {              // >=3 near-ties -> full rescue
            int slot = atomicAdd(&g_flag_count, 1);
            if (slot < CAP) { g_flag_rows[slot] = row; win = -1; }
        } else if (mv[1] < mv[0] + MARGIN) {       // exactly 2 candidates
            int slot = atomicAdd(&g_cand_count, 1);
            if (slot < CAP) { g_cand[slot] = make_int4(row, mi[0], mi[1], 0); win = -1; }
            else {
                int s2 = atomicAdd(&g_flag_count, 1);
                if (s2 < CAP) { g_flag_rows[s2] = row; win = -1; }
            }
        }
        s_win[tid] = win;
    }
    __syncthreads();

    // write output rows for clear winners (warp per row)
    for (int rr = wid; rr < BM; rr += 8) {
        const int w = s_win[rr];
        if (w >= 0) {
            const float4* src = reinterpret_cast<const float4*>(cb + (size_t)w * D);
            float4* dst = reinterpret_cast<float4*>(out + (size_t)(rowbase + rr) * D);
            #pragma unroll
            for (int j = 0; j < 4; ++j)
                dst[lane + j * 32] = src[lane + j * 32];
        }
    }
}

// ================= cand: exact 2-way rescore on reference fp32 grid =================
__global__ __launch_bounds__(256) void cand_kernel(
    const float* __restrict__ x,
    const float* __restrict__ cb,
    float* __restrict__ out)
{
    const int wid  = threadIdx.x >> 5;
    const int lane = threadIdx.x & 31;
    int total = g_cand_count;
    if (total > CAP) total = CAP;

    for (int e = blockIdx.x * 8 + wid; e < total; e += gridDim.x * 8) {
        const int4 ent = g_cand[e];
        const int row = ent.x;

        float xf[16];
        #pragma unroll
        for (int j = 0; j < 16; ++j) xf[j] = x[(size_t)row * D + lane + j * 32];
        double x2 = 0.0;
        #pragma unroll
        for (int j = 0; j < 16; ++j) x2 += (double)xf[j] * xf[j];
        #pragma unroll
        for (int o = 16; o; o >>= 1) x2 += __shfl_xor_sync(0xffffffffu, x2, o);
        const float x2f = (float)x2;

        float dv[2]; const int ci[2] = { ent.y, ent.z };
        #pragma unroll
        for (int t = 0; t < 2; ++t) {
            const float* cr = cb + (size_t)ci[t] * D;
            double dot = 0.0;
            #pragma unroll
            for (int j = 0; j < 16; ++j)
                dot += (double)xf[j] * (double)cr[lane + j * 32];
            #pragma unroll
            for (int o = 16; o; o >>= 1) dot += __shfl_xor_sync(0xffffffffu, dot, o);
            dv[t] = (x2f - 2.0f * (float)dot) + g_c2[ci[t]];
        }
        int winner = (dv[1] < dv[0] || (dv[1] == dv[0] && ci[1] < ci[0])) ? ci[1] : ci[0];

        const float4* src = reinterpret_cast<const float4*>(cb + (size_t)winner * D);
        float4* dst = reinterpret_cast<float4*>(out + (size_t)row * D);
        #pragma unroll
        for (int j = 0; j < 4; ++j)
            dst[lane + j * 32] = src[lane + j * 32];
    }
}

// ================= rescue: full fp64 rescore + output =================
__global__ __launch_bounds__(256) void rescue_kernel(
    const float* __restrict__ x,
    const float* __restrict__ cb,
    float* __restrict__ out)
{
    __shared__ float sx[D];
    __shared__ float wv[8];
    __shared__ int   wi[8];
    __shared__ int   s_win;

    const int tid  = threadIdx.x;
    const int wid  = tid >> 5;
    const int lane = tid & 31;
    int total = g_flag_count;
    if (total > CAP) total = CAP;

    for (int f = blockIdx.x; f < total; f += gridDim.x) {
        const int row = g_flag_rows[f];
        for (int i = tid; i < D; i += 256) sx[i] = x[(size_t)row * D + i];
        __syncthreads();

        double x2 = 0.0;
        for (int e = lane; e < D; e += 32) { double v = (double)sx[e]; x2 += v * v; }
        #pragma unroll
        for (int o = 16; o; o >>= 1) x2 += __shfl_xor_sync(0xffffffffu, x2, o);
        const float x2f = (float)x2;

        float bv = FLT_MAX;
        int   bi = 1 << 30;
        for (int cw = wid; cw < KCB; cw += 8) {
            const float* c = cb + (size_t)cw * D;
            double dot = 0.0;
            for (int e = lane; e < D; e += 32)
                dot += (double)sx[e] * (double)c[e];
            #pragma unroll
            for (int o = 16; o; o >>= 1) dot += __shfl_xor_sync(0xffffffffu, dot, o);
            float d2 = (x2f - 2.0f * (float)dot) + g_c2[cw];
            if (d2 < bv) { bv = d2; bi = cw; }
        }
        if (lane == 0) { wv[wid] = bv; wi[wid] = bi; }
        __syncthreads();
        if (tid == 0) {
            float fbv = wv[0]; int fbi = wi[0];
            #pragma unroll
            for (int t = 1; t < 8; ++t)
                if (wv[t] < fbv || (wv[t] == fbv && wi[t] < fbi)) { fbv = wv[t]; fbi = wi[t]; }
            s_win = fbi;
        }
        __syncthreads();
        const int w = s_win;
        if (tid < 128) {
            reinterpret_cast<float4*>(out + (size_t)row * D)[tid] =
                reinterpret_cast<const float4*>(cb + (size_t)w * D)[tid];
        }
        __syncthreads();
    }
}

extern "C" void kernel_launch(void* const* d_in, const int* in_sizes, int n_in,
                              void* d_out, int out_size) {
    const float* x  = (const float*)d_in[0];   // [65536, 512]
    const float* cb = (const float*)d_in[1];   // [1024, 512]
    float* out = (float*)d_out;
    int nrows = in_sizes[0] / D;               // 65536

    cudaFuncSetAttribute(vq_gemm_kernel,
                         cudaFuncAttributeMaxDynamicSharedMemorySize, SM_TOTAL);

    prep_x<<<(int)((size_t)nrows * D / 4 / 512), 512>>>(x);
    prep_cb<<<KCB * D / 4 / 512, 512>>>(cb);
    c2_kernel<<<KCB / 8, 256>>>(cb);
    vq_gemm_kernel<<<nrows / BM, NTH, SM_TOTAL>>>(cb, out);
    cand_kernel<<<296, 256>>>(x, cb, out);
    rescue_kernel<<<296, 256>>>(x, cb, out);
}